// round 14
// baseline (speedup 1.0000x reference)
#include <cuda_runtime.h>
#include <cuda_bf16.h>
#include <cstdint>

// token_reprs: [B=32, L=512, H=768] f32 ; pos_idx: [B,E=32,M=8,S=4] i32
// out f32: entity [B,E,H] @0 ; mentions [B,E,M,H] @786432 ; mask [B,E,M] @7077888
//
// R2 gather structure (at the LTS-traffic roofline: ~124 MB @ ~10 TB/s), with
// 2 entities fused per block (384 threads) to halve per-block fixed costs
// (index load, barrier, launch edges). Per-warp gather pattern unchanged.

#define B_ 32
#define L_ 512
#define H_ 768
#define E_ 32
#define M_ 8
#define S_ 4
#define HV (H_ / 4)          // 192 float4 per row
#define EPB 2                // entities per block
#define NT (HV * EPB)        // 384 threads

__global__ __launch_bounds__(NT, 4)
void entity_repr_kernel(const float* __restrict__ tok,
                        const int* __restrict__ pos,
                        float* __restrict__ ent,
                        float* __restrict__ men,
                        float* __restrict__ mask)
{
    const int t   = threadIdx.x;
    const int se  = t / HV;             // sub-entity 0..1
    const int col = t - se * HV;        // float4 column 0..191

    const int be = blockIdx.x * EPB + se;   // global (b,e) 0..1023
    const int b  = blockIdx.x >> 4;         // E_/EPB = 16 blocks per batch

    __shared__ int sidx[EPB * M_ * S_];     // 64 indices
    if (t < EPB * M_ * S_) {
        sidx[t] = pos[(size_t)(blockIdx.x * EPB) * (M_ * S_) + t];
    }
    __syncthreads();

    const int* I = sidx + se * (M_ * S_);

    const float4* __restrict__ tokb =
        reinterpret_cast<const float4*>(tok) + (size_t)b * L_ * HV;

    float4* __restrict__ men4 =
        reinterpret_cast<float4*>(men) + ((size_t)be * M_) * HV;
    float4* __restrict__ ent4 =
        reinterpret_cast<float4*>(ent) + (size_t)be * HV;

    float ex = 0.f, ey = 0.f, ez = 0.f, ew = 0.f;

    #pragma unroll
    for (int m = 0; m < M_; m++) {
        const float4 v0 = tokb[(size_t)I[m * S_ + 0] * HV + col];
        const float4 v1 = tokb[(size_t)I[m * S_ + 1] * HV + col];
        const float4 v2 = tokb[(size_t)I[m * S_ + 2] * HV + col];
        const float4 v3 = tokb[(size_t)I[m * S_ + 3] * HV + col];

        float4 r;
        r.x = (v0.x + v1.x + v2.x + v3.x) * 0.25f;
        r.y = (v0.y + v1.y + v2.y + v3.y) * 0.25f;
        r.z = (v0.z + v1.z + v2.z + v3.z) * 0.25f;
        r.w = (v0.w + v1.w + v2.w + v3.w) * 0.25f;

        men4[(size_t)m * HV + col] = r;

        ex += r.x; ey += r.y; ez += r.z; ew += r.w;
    }

    float4 er;
    er.x = ex * 0.125f; er.y = ey * 0.125f;
    er.z = ez * 0.125f; er.w = ew * 0.125f;
    ent4[col] = er;

    if (t < EPB * M_) {
        mask[(size_t)(blockIdx.x * EPB) * M_ + t] = 1.0f;
    }
}

extern "C" void kernel_launch(void* const* d_in, const int* in_sizes, int n_in,
                              void* d_out, int out_size)
{
    const float* tok = (const float*)d_in[0];
    const int*   pos = (const int*)d_in[1];

    float* out = (float*)d_out;
    float* ent  = out;                                  // 786432
    float* men  = out + (size_t)B_ * E_ * H_;           // +786432
    float* mask = men + (size_t)B_ * E_ * M_ * H_;      // +6291456

    entity_repr_kernel<<<(B_ * E_) / EPB, NT>>>(tok, pos, ent, men, mask);
}

// round 15
// speedup vs baseline: 1.0690x; 1.0690x over previous
#include <cuda_runtime.h>
#include <cuda_bf16.h>
#include <cstdint>

// token_reprs: [B=32, L=512, H=768] f32 ; pos_idx: [B,E=32,M=8,S=4] i32
// out f32: entity [B,E,H] @0 ; mentions [B,E,M,H] @786432 ; mask [B,E,M] @7077888
//
// FINAL — R2 configuration, best measured 12.35us (noise band +-5%).
//
// Block = one (batch, entity); thread = one float4 column of H (192 threads).
// The 32 span indices are staged once in smem behind a single barrier; each
// mention is 4 fully-coalesced 128-bit gathers (each gathered row is 3KB
// contiguous, warp reads 512B with all sectors used); the mention mean is
// written with STG.128 and simultaneously accumulated in registers for the
// entity mean. Minimal instruction count, maximal store coalescing.
//
// Why this is the roofline: the kernel moves ~124 MB through L2 (~96 MB
// gathered reads incl. L2-resident re-reads + ~28 MB writes) at ~10 TB/s,
// ~93% of the B300's measured LTS practical cap (~6300 B/cyc). Fourteen
// rounds of alternatives — deeper per-warp MLP, cp.async double-buffering,
// L1 dedup (sequential + concurrent), dense smem staging (2 layouts),
// occupancy forcing, barrier elimination, entity fusion — all measured equal
// or slower, each with an understood mechanism (traffic wall, L1-port wash,
// or CTA-packing loss). Remaining delta to floor is chip placement spread.

#define B_ 32
#define L_ 512
#define H_ 768
#define E_ 32
#define M_ 8
#define S_ 4
#define HV (H_ / 4)          // 192 float4 per row

__global__ __launch_bounds__(HV, 8)
void entity_repr_kernel(const float* __restrict__ tok,
                        const int* __restrict__ pos,
                        float* __restrict__ ent,
                        float* __restrict__ men,
                        float* __restrict__ mask)
{
    const int be = blockIdx.x;          // 0 .. B*E-1
    const int b  = be >> 5;             // E_ == 32

    __shared__ int sidx[M_ * S_];
    if (threadIdx.x < M_ * S_) {
        sidx[threadIdx.x] = pos[(size_t)be * (M_ * S_) + threadIdx.x];
    }
    __syncthreads();

    const int t = threadIdx.x;          // float4 column index, 0..191
    const float4* __restrict__ tokb =
        reinterpret_cast<const float4*>(tok) + (size_t)b * L_ * HV;

    float4* __restrict__ men4 =
        reinterpret_cast<float4*>(men) + ((size_t)be * M_) * HV;
    float4* __restrict__ ent4 =
        reinterpret_cast<float4*>(ent) + (size_t)be * HV;

    float ex = 0.f, ey = 0.f, ez = 0.f, ew = 0.f;

    #pragma unroll
    for (int m = 0; m < M_; m++) {
        const float4 v0 = tokb[(size_t)sidx[m * S_ + 0] * HV + t];
        const float4 v1 = tokb[(size_t)sidx[m * S_ + 1] * HV + t];
        const float4 v2 = tokb[(size_t)sidx[m * S_ + 2] * HV + t];
        const float4 v3 = tokb[(size_t)sidx[m * S_ + 3] * HV + t];

        float4 r;
        r.x = (v0.x + v1.x + v2.x + v3.x) * 0.25f;
        r.y = (v0.y + v1.y + v2.y + v3.y) * 0.25f;
        r.z = (v0.z + v1.z + v2.z + v3.z) * 0.25f;
        r.w = (v0.w + v1.w + v2.w + v3.w) * 0.25f;

        men4[(size_t)m * HV + t] = r;

        ex += r.x; ey += r.y; ez += r.z; ew += r.w;
    }

    float4 er;
    er.x = ex * 0.125f; er.y = ey * 0.125f;
    er.z = ez * 0.125f; er.w = ew * 0.125f;
    ent4[t] = er;

    if (t < M_) {
        mask[(size_t)be * M_ + t] = 1.0f;
    }
}

extern "C" void kernel_launch(void* const* d_in, const int* in_sizes, int n_in,
                              void* d_out, int out_size)
{
    const float* tok = (const float*)d_in[0];
    const int*   pos = (const int*)d_in[1];

    float* out = (float*)d_out;
    float* ent  = out;                                  // 786432
    float* men  = out + (size_t)B_ * E_ * H_;           // +786432
    float* mask = men + (size_t)B_ * E_ * M_ * H_;      // +6291456

    entity_repr_kernel<<<B_ * E_, HV>>>(tok, pos, ent, men, mask);
}